// round 4
// baseline (speedup 1.0000x reference)
#include <cuda_runtime.h>
#include <cuda_bf16.h>
#include <cstdint>

// ---------------------------------------------------------------------------
// SpatialNonIntersectionAxiom: pairwise segment proximity loss over E edges.
// out[0]=loss, out[1..1+E^2)=violation_mask, out[1+E^2..1+2E^2)=scores (f32).
//
// Alignment note: global float index of mask[i][j] is 1 + i*E + j. With
// E % 4 == 0, that is 16B-aligned iff j % 4 == 3. The vector kernel therefore
// covers j in {4c+3..4c+6}; leftover columns {0,1,2} and the tail are done
// scalar by edge_kernel.
// ---------------------------------------------------------------------------

#define MAXE 8192
#define BLK  256
#define TI   4   // i-rows per block

// Per-edge precomputed tables (__device__ globals: no allocs allowed)
__device__ float4 g_eA[MAXE];   // p_src.x, p_src.y, d1.x, d1.y
__device__ float4 g_eB[MAXE];   // mid.x, mid.y, half, sq(clamped)
__device__ float2 g_eC[MAXE];   // d1·p_src, packed(batch<<24|src<<12|dst) bits

// Spread-address loss accumulators (fixed-point 2^-40: deterministic ints)
__device__ unsigned long long g_rowAcc[MAXE / TI + 1];
__device__ unsigned long long g_rowCnt[MAXE / TI + 1];

// ---------------- pair math (shared by both kernels) -----------------------
__device__ __forceinline__ float pair_loss(
    const float4& iA, const float4& iB, const float2& iC,
    const float4& jA, const float4& jB, const float2& jC,
    int i, int j, bool jvalid, int E, unsigned int* cnt)
{
    unsigned int pi = __float_as_uint(iC.y);
    unsigned int pj = __float_as_uint(jC.y);
    if (!jvalid || i >= E || j <= i || ((pi ^ pj) >> 24) != 0u) return 0.0f;
    unsigned int si = (pi >> 12) & 0xFFFu, di = pi & 0xFFFu;
    unsigned int sj = (pj >> 12) & 0xFFFu, dj = pj & 0xFFFu;
    if ((si == sj) | (si == dj) | (di == sj) | (di == dj)) return 0.0f;
    float dx = iB.x - jB.x;
    float dy = iB.y - jB.y;
    float d2 = dx * dx + dy * dy;
    float reach = iB.z + jB.z + 0.15f;
    if (d2 >= reach * reach) return 0.0f;   // dist < reach (reach > 0)
    (*cnt)++;                               // candidate mask counts here
    float A  = iB.w;                        // sq_i (clamped)
    float Ee = jB.w;                        // sq_j (clamped)
    float b  = iA.z * jA.z + iA.w * jA.w;
    float c  = iC.x - (iA.z * jA.x + iA.w * jA.y);
    float f  = (iA.x * jA.z + iA.y * jA.w) - jC.x;
    float denom = fmaxf(A * Ee - b * b, 1e-12f);
    float s = __fdiv_rn(b * f - c * Ee, denom);
    s = fminf(fmaxf(s, 0.0f), 1.0f);
    float t = fminf(fmaxf(__fdiv_rn(b * s + f, Ee), 0.0f), 1.0f);
    s = fminf(fmaxf(__fdiv_rn(b * t - c, A), 0.0f), 1.0f);
    float cax = iA.x + s * iA.z;
    float cay = iA.y + s * iA.w;
    float cbx = jA.x + t * jA.z;
    float cby = jA.y + t * jA.w;
    float ddx = cax - cbx, ddy = cay - cby;
    float dmin = __fsqrt_rn(ddx * ddx + ddy * ddy);
    return fmaxf(0.001f - dmin, 0.0f);
}

__global__ void prep_kernel(const float* __restrict__ pos,
                            const int* __restrict__ ei,
                            int E, int N, int nodes, int nrows) {
    int e = blockIdx.x * blockDim.x + threadIdx.x;
    if (e <= nrows) { g_rowAcc[e] = 0ull; g_rowCnt[e] = 0ull; }
    if (e >= E) return;
    int s = ei[e];
    int d = ei[E + e];
    s = min(max(s, 0), nodes - 1);
    d = min(max(d, 0), nodes - 1);
    float psx = pos[2 * s],  psy = pos[2 * s + 1];
    float pdx = pos[2 * d],  pdy = pos[2 * d + 1];
    float d1x = pdx - psx,   d1y = pdy - psy;
    float rawsq = d1x * d1x + d1y * d1y;
    float sq    = fmaxf(rawsq, 1e-12f);
    float half  = __fsqrt_rn(rawsq) * 0.5f;
    float midx  = (psx + pdx) * 0.5f;
    float midy  = (psy + pdy) * 0.5f;
    float dda   = d1x * psx + d1y * psy;
    unsigned int b = (unsigned int)(s / N);
    unsigned int packed = (b << 24) | (((unsigned int)s & 0xFFFu) << 12)
                        | ((unsigned int)d & 0xFFFu);
    g_eA[e] = make_float4(psx, psy, d1x, d1y);
    g_eB[e] = make_float4(midx, midy, half, sq);
    g_eC[e] = make_float2(dda, __uint_as_float(packed));
}

// Vector kernel: j-quads {4c+3..4c+6}, aligned float4 stores.
__global__ void __launch_bounds__(BLK)
pair_kernel(float* __restrict__ out, int E, int K, int writeBig) {
    const int chunk = blockIdx.x * BLK + threadIdx.x;
    if (chunk >= K) return;
    const int i0 = blockIdx.y * TI;
    const int j0 = 3 + 4 * chunk;

    float* __restrict__ outMask  = out + 1;
    float* __restrict__ outScore = out + 1 + (size_t)E * (size_t)E;

    // Block's max j: last chunk in this block (clamped to K-1)
    const int lastChunk = min((blockIdx.x + 1) * BLK, K) - 1;
    const int jBlockMax = 3 + 4 * lastChunk + 3;

    // --- Fast path: whole block strictly lower-triangle => zeros ---
    if (jBlockMax <= i0) {
        if (writeBig) {
            float4 z = make_float4(0.f, 0.f, 0.f, 0.f);
#pragma unroll
            for (int a = 0; a < TI; a++) {
                int i = i0 + a;
                if (i >= E) break;
                size_t off = (size_t)i * (size_t)E + (size_t)j0;
                *(float4*)(outMask  + off) = z;
                *(float4*)(outScore + off) = z;
            }
        }
        return;
    }

    float4 iA[TI], iB[TI]; float2 iC[TI];
#pragma unroll
    for (int a = 0; a < TI; a++) {
        int ic = min(i0 + a, E - 1);
        iA[a] = g_eA[ic]; iB[a] = g_eB[ic]; iC[a] = g_eC[ic];
    }

    float mval[TI][4], sval[TI][4];
    unsigned long long accQ = 0ull;
    unsigned int       cnt  = 0u;

#pragma unroll
    for (int jj = 0; jj < 4; jj++) {
        int j = j0 + jj;                 // in-range by construction (E%4==0)
        float4 jA = g_eA[j];
        float4 jB = g_eB[j];
        float2 jC = g_eC[j];
#pragma unroll
        for (int a = 0; a < TI; a++) {
            int i = i0 + a;
            float pl = pair_loss(iA[a], iB[a], iC[a], jA, jB, jC,
                                 i, j, true, E, &cnt);
            if (pl > 0.0f)
                accQ += (unsigned long long)
                    __double2ll_rn((double)pl * 1099511627776.0);
            mval[a][jj] = (pl > 0.0f) ? 1.0f : 0.0f;
            sval[a][jj] = pl;
        }
    }

    if (writeBig) {
#pragma unroll
        for (int a = 0; a < TI; a++) {
            int i = i0 + a;
            if (i >= E) break;
            size_t off = (size_t)i * (size_t)E + (size_t)j0;
            *(float4*)(outMask  + off) = *(float4*)mval[a];
            *(float4*)(outScore + off) = *(float4*)sval[a];
        }
    }

    // Block reduction -> one spread atomic per row-block
#pragma unroll
    for (int o = 16; o; o >>= 1) {
        accQ += __shfl_xor_sync(0xffffffffu, accQ, o);
        cnt  += __shfl_xor_sync(0xffffffffu, cnt,  o);
    }
    __shared__ unsigned long long sQ[BLK / 32];
    __shared__ unsigned int       sC[BLK / 32];
    int w = threadIdx.x >> 5;
    if ((threadIdx.x & 31) == 0) { sQ[w] = accQ; sC[w] = cnt; }
    __syncthreads();
    if (threadIdx.x == 0) {
        unsigned long long q = 0ull; unsigned int c = 0u;
#pragma unroll
        for (int k = 0; k < BLK / 32; k++) { q += sQ[k]; c += sC[k]; }
        if (q | (unsigned long long)c) {
            atomicAdd(&g_rowAcc[blockIdx.y], q);
            atomicAdd(&g_rowCnt[blockIdx.y], (unsigned long long)c);
        }
    }
}

// Scalar kernel for leftover columns: j in {0,1,2} and [3+4K, E).
__global__ void edge_kernel(float* __restrict__ out, int E, int K,
                            int ncols, int writeBig) {
    int idx = blockIdx.x * blockDim.x + threadIdx.x;
    int total = E * ncols;
    if (idx >= total) return;
    int i    = idx / ncols;
    int cidx = idx - i * ncols;
    int j    = (cidx < 3 && K > 0) ? cidx : (3 + 4 * K + (cidx - (K > 0 ? 3 : 0)));
    if (j >= E) return;

    float4 iA = g_eA[i], iB = g_eB[i]; float2 iC = g_eC[i];
    float4 jA = g_eA[j], jB = g_eB[j]; float2 jC = g_eC[j];
    unsigned int cnt = 0u;
    float pl = pair_loss(iA, iB, iC, jA, jB, jC, i, j, true, E, &cnt);

    if (writeBig) {
        size_t off = (size_t)i * (size_t)E + (size_t)j;
        out[1 + off] = (pl > 0.0f) ? 1.0f : 0.0f;
        out[1 + (size_t)E * (size_t)E + off] = pl;
    }
    if (cnt) {
        atomicAdd(&g_rowCnt[i / TI], (unsigned long long)cnt);
        if (pl > 0.0f)
            atomicAdd(&g_rowAcc[i / TI], (unsigned long long)
                      __double2ll_rn((double)pl * 1099511627776.0));
    }
}

__global__ void finalize_kernel(float* __restrict__ out, int nrows) {
    __shared__ unsigned long long sQ[256];
    __shared__ unsigned long long sC[256];
    unsigned long long q = 0ull, c = 0ull;
    for (int k = threadIdx.x; k <= nrows; k += 256) {
        q += g_rowAcc[k];
        c += g_rowCnt[k];
    }
    sQ[threadIdx.x] = q; sC[threadIdx.x] = c;
    __syncthreads();
    for (int st = 128; st; st >>= 1) {
        if (threadIdx.x < st) {
            sQ[threadIdx.x] += sQ[threadIdx.x + st];
            sC[threadIdx.x] += sC[threadIdx.x + st];
        }
        __syncthreads();
    }
    if (threadIdx.x == 0) {
        double sum = (double)sQ[0] * (1.0 / 1099511627776.0);
        unsigned long long n = sC[0] ? sC[0] : 1ull;
        out[0] = (float)(sum / (double)n);
    }
}

extern "C" void kernel_launch(void* const* d_in, const int* in_sizes, int n_in,
                              void* d_out, int out_size) {
    const float* pos = (const float*)d_in[0];
    // d_in[1] = adjacency: unused by the reference computation
    const int*   ei  = (const int*)d_in[2];

    int E     = in_sizes[2] / 2;
    int nodes = in_sizes[0] / 2;
    int N     = in_sizes[1] / nodes;
    int nrows = (E + TI - 1) / TI;

    long long need = 1ll + 2ll * (long long)E * (long long)E;
    int writeBig = ((long long)out_size >= need) ? 1 : 0;

    // Vector region only valid when E % 4 == 0 (alignment proof above)
    int K = (E % 4 == 0 && E > 4) ? (E - 3) / 4 : 0;
    int ncols = (K > 0) ? (3 + (E - (3 + 4 * K))) : E;

    float* out = (float*)d_out;

    int prepThreads = 128;
    int prepWork = max(E, nrows + 1);
    prep_kernel<<<(prepWork + prepThreads - 1) / prepThreads, prepThreads>>>(
        pos, ei, E, N, nodes, nrows);

    if (K > 0) {
        dim3 grid((K + BLK - 1) / BLK, nrows);
        pair_kernel<<<grid, BLK>>>(out, E, K, writeBig);
    }
    int edgeTotal = E * ncols;
    edge_kernel<<<(edgeTotal + 255) / 256, 256>>>(out, E, K, ncols, writeBig);

    finalize_kernel<<<1, 256>>>(out, nrows);
}

// round 5
// speedup vs baseline: 1.1025x; 1.1025x over previous
#include <cuda_runtime.h>
#include <cuda_bf16.h>
#include <cstdint>

// ---------------------------------------------------------------------------
// SpatialNonIntersectionAxiom: pairwise segment proximity loss over E edges.
// out[0]=loss, out[1..1+E^2)=violation_mask, out[1+E^2..1+2E^2)=scores (f32).
//
// Alignment: global float index of mask[i][j] is 1 + i*E + j; with E%4==0 it
// is 16B-aligned iff j % 4 == 3. Vector kernel covers j in {4c+3..4c+6};
// leftover columns handled scalar by edge_kernel.
// ---------------------------------------------------------------------------

#define MAXE 8192
#define BLK  256
#define TI   8   // i-rows per block (row loop is sequential; no reg growth)

// Per-edge precomputed tables (__device__ globals: no allocs allowed)
__device__ float4 g_eA[MAXE];   // p_src.x, p_src.y, d1.x, d1.y
__device__ float4 g_eB[MAXE];   // mid.x, mid.y, half, sq(clamped)
__device__ float2 g_eC[MAXE];   // d1·p_src, packed(batch<<24|src<<12|dst) bits

// Spread-address loss accumulators (fixed-point 2^-40: deterministic ints)
__device__ unsigned long long g_rowAcc[MAXE / 4 + 2];
__device__ unsigned long long g_rowCnt[MAXE / 4 + 2];

// ---------------- pair math (shared by both kernels) -----------------------
__device__ __forceinline__ float pair_loss(
    const float4& iA, const float4& iB, const float2& iC,
    const float4& jA, const float4& jB, const float2& jC,
    int i, int j, unsigned int* cnt)
{
    unsigned int pi = __float_as_uint(iC.y);
    unsigned int pj = __float_as_uint(jC.y);
    if (j <= i || ((pi ^ pj) >> 24) != 0u) return 0.0f;
    unsigned int si = (pi >> 12) & 0xFFFu, di = pi & 0xFFFu;
    unsigned int sj = (pj >> 12) & 0xFFFu, dj = pj & 0xFFFu;
    if ((si == sj) | (si == dj) | (di == sj) | (di == dj)) return 0.0f;
    float dx = iB.x - jB.x;
    float dy = iB.y - jB.y;
    float d2 = dx * dx + dy * dy;
    float reach = iB.z + jB.z + 0.15f;
    if (d2 >= reach * reach) return 0.0f;   // dist < reach (reach > 0)
    (*cnt)++;                               // candidate mask counts here
    float A  = iB.w;                        // sq_i (clamped)
    float Ee = jB.w;                        // sq_j (clamped)
    float b  = iA.z * jA.z + iA.w * jA.w;
    float c  = iC.x - (iA.z * jA.x + iA.w * jA.y);
    float f  = (iA.x * jA.z + iA.y * jA.w) - jC.x;
    float denom = fmaxf(A * Ee - b * b, 1e-12f);
    float s = __fdiv_rn(b * f - c * Ee, denom);
    s = fminf(fmaxf(s, 0.0f), 1.0f);
    float t = fminf(fmaxf(__fdiv_rn(b * s + f, Ee), 0.0f), 1.0f);
    s = fminf(fmaxf(__fdiv_rn(b * t - c, A), 0.0f), 1.0f);
    float cax = iA.x + s * iA.z;
    float cay = iA.y + s * iA.w;
    float cbx = jA.x + t * jA.z;
    float cby = jA.y + t * jA.w;
    float ddx = cax - cbx, ddy = cay - cby;
    float dmin = __fsqrt_rn(ddx * ddx + ddy * ddy);
    return fmaxf(0.001f - dmin, 0.0f);
}

__global__ void prep_kernel(const float* __restrict__ pos,
                            const int* __restrict__ ei,
                            int E, int N, int nodes, int naccs) {
    int e = blockIdx.x * blockDim.x + threadIdx.x;
    if (e < naccs) { g_rowAcc[e] = 0ull; g_rowCnt[e] = 0ull; }
    if (e >= E) return;
    int s = ei[e];
    int d = ei[E + e];
    s = min(max(s, 0), nodes - 1);
    d = min(max(d, 0), nodes - 1);
    float psx = pos[2 * s],  psy = pos[2 * s + 1];
    float pdx = pos[2 * d],  pdy = pos[2 * d + 1];
    float d1x = pdx - psx,   d1y = pdy - psy;
    float rawsq = d1x * d1x + d1y * d1y;
    float sq    = fmaxf(rawsq, 1e-12f);
    float half  = __fsqrt_rn(rawsq) * 0.5f;
    float midx  = (psx + pdx) * 0.5f;
    float midy  = (psy + pdy) * 0.5f;
    float dda   = d1x * psx + d1y * psy;
    unsigned int b = (unsigned int)(s / N);
    unsigned int packed = (b << 24) | (((unsigned int)s & 0xFFFu) << 12)
                        | ((unsigned int)d & 0xFFFu);
    g_eA[e] = make_float4(psx, psy, d1x, d1y);
    g_eB[e] = make_float4(midx, midy, half, sq);
    g_eC[e] = make_float2(dda, __uint_as_float(packed));
}

// Vector kernel: j-quads {4c+3..4c+6}, aligned float4 stores, row loop outer.
__global__ void __launch_bounds__(BLK)
pair_kernel(float* __restrict__ out, int E, int K, int writeBig) {
    const int chunk = blockIdx.x * BLK + threadIdx.x;
    if (chunk >= K) return;
    const int i0 = blockIdx.y * TI;
    const int j0 = 3 + 4 * chunk;

    float* __restrict__ outMask  = out + 1;
    float* __restrict__ outScore = out + 1 + (size_t)E * (size_t)E;

    const int lastChunk = min((blockIdx.x + 1) * BLK, K) - 1;
    const int jBlockMax = 3 + 4 * lastChunk + 3;

    // --- Fast path: whole block strictly lower-triangle => zeros ---
    if (jBlockMax <= i0) {
        if (writeBig) {
            float4 z = make_float4(0.f, 0.f, 0.f, 0.f);
#pragma unroll
            for (int a = 0; a < TI; a++) {
                int i = i0 + a;
                if (i >= E) break;
                size_t off = (size_t)i * (size_t)E + (size_t)j0;
                *(float4*)(outMask  + off) = z;
                *(float4*)(outScore + off) = z;
            }
        }
        return;
    }

    // Load the j-quad ONCE into registers (amortized over TI rows)
    float4 jA[4], jB[4]; float2 jC[4];
#pragma unroll
    for (int jj = 0; jj < 4; jj++) {
        jA[jj] = g_eA[j0 + jj];
        jB[jj] = g_eB[j0 + jj];
        jC[jj] = g_eC[j0 + jj];
    }

    unsigned long long accQ = 0ull;
    unsigned int       cnt  = 0u;

    // Row loop outermost: i-record loaded per row (warp-uniform broadcast),
    // outputs stored immediately -> minimal live register set, no spills.
#pragma unroll 1
    for (int a = 0; a < TI; a++) {
        int i = i0 + a;
        if (i >= E) break;
        float4 iA = g_eA[i], iB = g_eB[i];
        float2 iC = g_eC[i];
        float m4[4], s4[4];
#pragma unroll
        for (int jj = 0; jj < 4; jj++) {
            float pl = pair_loss(iA, iB, iC, jA[jj], jB[jj], jC[jj],
                                 i, j0 + jj, &cnt);
            if (pl > 0.0f)
                accQ += (unsigned long long)
                    __double2ll_rn((double)pl * 1099511627776.0);
            m4[jj] = (pl > 0.0f) ? 1.0f : 0.0f;
            s4[jj] = pl;
        }
        if (writeBig) {
            size_t off = (size_t)i * (size_t)E + (size_t)j0;
            *(float4*)(outMask  + off) = *(float4*)m4;
            *(float4*)(outScore + off) = *(float4*)s4;
        }
    }

    // Block reduction -> one spread atomic per row-block
#pragma unroll
    for (int o = 16; o; o >>= 1) {
        accQ += __shfl_xor_sync(0xffffffffu, accQ, o);
        cnt  += __shfl_xor_sync(0xffffffffu, cnt,  o);
    }
    __shared__ unsigned long long sQ[BLK / 32];
    __shared__ unsigned int       sC[BLK / 32];
    int w = threadIdx.x >> 5;
    if ((threadIdx.x & 31) == 0) { sQ[w] = accQ; sC[w] = cnt; }
    __syncthreads();
    if (threadIdx.x == 0) {
        unsigned long long q = 0ull; unsigned int c = 0u;
#pragma unroll
        for (int k = 0; k < BLK / 32; k++) { q += sQ[k]; c += sC[k]; }
        if (q | (unsigned long long)c) {
            atomicAdd(&g_rowAcc[blockIdx.y], q);
            atomicAdd(&g_rowCnt[blockIdx.y], (unsigned long long)c);
        }
    }
}

// Scalar kernel for leftover columns: j in {0,1,2} and [3+4K, E).
__global__ void edge_kernel(float* __restrict__ out, int E, int K,
                            int ncols, int nrows, int writeBig) {
    int idx = blockIdx.x * blockDim.x + threadIdx.x;
    int total = E * ncols;
    if (idx >= total) return;
    int i    = idx / ncols;
    int cidx = idx - i * ncols;
    int j    = (cidx < 3 && K > 0) ? cidx : (3 + 4 * K + (cidx - (K > 0 ? 3 : 0)));
    if (j >= E) return;

    float4 iA = g_eA[i], iB = g_eB[i]; float2 iC = g_eC[i];
    float4 jA = g_eA[j], jB = g_eB[j]; float2 jC = g_eC[j];
    unsigned int cnt = 0u;
    float pl = pair_loss(iA, iB, iC, jA, jB, jC, i, j, &cnt);

    if (writeBig) {
        size_t off = (size_t)i * (size_t)E + (size_t)j;
        out[1 + off] = (pl > 0.0f) ? 1.0f : 0.0f;
        out[1 + (size_t)E * (size_t)E + off] = pl;
    }
    if (cnt) {
        int slot = nrows + (i & 15);   // spread past the row accumulators
        atomicAdd(&g_rowCnt[slot], (unsigned long long)cnt);
        if (pl > 0.0f)
            atomicAdd(&g_rowAcc[slot], (unsigned long long)
                      __double2ll_rn((double)pl * 1099511627776.0));
    }
}

__global__ void finalize_kernel(float* __restrict__ out, int naccs) {
    __shared__ unsigned long long sQ[256];
    __shared__ unsigned long long sC[256];
    unsigned long long q = 0ull, c = 0ull;
    for (int k = threadIdx.x; k < naccs; k += 256) {
        q += g_rowAcc[k];
        c += g_rowCnt[k];
    }
    sQ[threadIdx.x] = q; sC[threadIdx.x] = c;
    __syncthreads();
    for (int st = 128; st; st >>= 1) {
        if (threadIdx.x < st) {
            sQ[threadIdx.x] += sQ[threadIdx.x + st];
            sC[threadIdx.x] += sC[threadIdx.x + st];
        }
        __syncthreads();
    }
    if (threadIdx.x == 0) {
        double sum = (double)sQ[0] * (1.0 / 1099511627776.0);
        unsigned long long n = sC[0] ? sC[0] : 1ull;
        out[0] = (float)(sum / (double)n);
    }
}

extern "C" void kernel_launch(void* const* d_in, const int* in_sizes, int n_in,
                              void* d_out, int out_size) {
    const float* pos = (const float*)d_in[0];
    // d_in[1] = adjacency: unused by the reference computation
    const int*   ei  = (const int*)d_in[2];

    int E     = in_sizes[2] / 2;
    int nodes = in_sizes[0] / 2;
    int N     = in_sizes[1] / nodes;
    int nrows = (E + TI - 1) / TI;        // vector-kernel accumulator rows
    int naccs = nrows + 16;               // + edge-kernel spread slots

    long long need = 1ll + 2ll * (long long)E * (long long)E;
    int writeBig = ((long long)out_size >= need) ? 1 : 0;

    // Vector region only valid when E % 4 == 0 (alignment proof above)
    int K = (E % 4 == 0 && E > 4) ? (E - 3) / 4 : 0;
    int ncols = (K > 0) ? (3 + (E - (3 + 4 * K))) : E;

    float* out = (float*)d_out;

    int prepThreads = 128;
    int prepWork = max(E, naccs);
    prep_kernel<<<(prepWork + prepThreads - 1) / prepThreads, prepThreads>>>(
        pos, ei, E, N, nodes, naccs);

    if (K > 0) {
        dim3 grid((K + BLK - 1) / BLK, nrows);
        pair_kernel<<<grid, BLK>>>(out, E, K, writeBig);
    }
    int edgeTotal = E * ncols;
    edge_kernel<<<(edgeTotal + 255) / 256, 256>>>(out, E, K, ncols, nrows, writeBig);

    finalize_kernel<<<1, 256>>>(out, naccs);
}

// round 6
// speedup vs baseline: 1.4618x; 1.3259x over previous
#include <cuda_runtime.h>
#include <cuda_bf16.h>
#include <cstdint>

// ---------------------------------------------------------------------------
// SpatialNonIntersectionAxiom — sparse formulation.
// out[0]=loss, out[1..1+E^2)=violation_mask, out[1+E^2..1+2E^2)=scores (f32).
//
// Only same-batch pairs can be candidates; only pairs with dmin < EPSILON
// produce nonzero outputs (~1% of entries). So: streaming zero-fill of both
// planes, then batch-list-driven sparse compute with scattered stores.
// ---------------------------------------------------------------------------

#define MAXE 8192
#define MAXB 64
#define BLK  256
#define TI   8
#define NACC (MAXE / TI + 32)

// Per-edge tables (__device__ globals: no allocs allowed)
__device__ float4 g_eA[MAXE];             // p_src.x, p_src.y, d1.x, d1.y
__device__ float4 g_eB[MAXE];             // mid.x, mid.y, half, sq(clamped)
__device__ float2 g_eC[MAXE];             // d1·p_src, packed(b<<24|src<<12|dst)
__device__ int    g_blist[MAXB * MAXE];   // per-batch edge lists
__device__ int    g_bcnt[MAXB];           // per-batch counts
// Fixed-point (2^-40) deterministic loss accumulators, spread addresses
__device__ unsigned long long g_Acc[NACC];
__device__ unsigned long long g_Cnt[NACC];

// 1) Streaming zero-fill of output planes + bookkeeping reset.
__global__ void fill_kernel(float* __restrict__ out,
                            long long start, long long end, int writeBig) {
    long long idx = blockIdx.x * (long long)blockDim.x + threadIdx.x;
    long long nth = gridDim.x * (long long)blockDim.x;
    if (idx < MAXB) g_bcnt[idx] = 0;
    if (idx < NACC) { g_Acc[idx] = 0ull; g_Cnt[idx] = 0ull; }
    if (!writeBig) return;
    long long aStart = (start + 3) & ~3ll;
    long long aEnd   = end & ~3ll;
    if (idx == 0) {   // scalar head/tail (few elements)
        for (long long k = start; k < aStart && k < end; k++) out[k] = 0.f;
        for (long long k = (aEnd > start ? aEnd : start); k < end; k++) out[k] = 0.f;
    }
    if (aEnd <= aStart) return;
    float4 z = make_float4(0.f, 0.f, 0.f, 0.f);
    long long nvec = (aEnd - aStart) >> 2;
    float* base = out + aStart;
    for (long long v = idx; v < nvec; v += nth)
        *(float4*)(base + 4 * v) = z;
}

// 2) Per-edge tables + per-batch lists (order-independent downstream).
__global__ void prep_kernel(const float* __restrict__ pos,
                            const int* __restrict__ ei,
                            int E, int N, int nodes) {
    int e = blockIdx.x * blockDim.x + threadIdx.x;
    if (e >= E) return;
    int s = ei[e];
    int d = ei[E + e];
    s = min(max(s, 0), nodes - 1);
    d = min(max(d, 0), nodes - 1);
    float psx = pos[2 * s],  psy = pos[2 * s + 1];
    float pdx = pos[2 * d],  pdy = pos[2 * d + 1];
    float d1x = pdx - psx,   d1y = pdy - psy;
    float rawsq = d1x * d1x + d1y * d1y;
    float sq    = fmaxf(rawsq, 1e-12f);
    float half  = __fsqrt_rn(rawsq) * 0.5f;
    float midx  = (psx + pdx) * 0.5f;
    float midy  = (psy + pdy) * 0.5f;
    float dda   = d1x * psx + d1y * psy;
    int b = min(s / N, MAXB - 1);
    unsigned int packed = ((unsigned int)b << 24)
                        | (((unsigned int)s & 0xFFFu) << 12)
                        | ((unsigned int)d & 0xFFFu);
    g_eA[e] = make_float4(psx, psy, d1x, d1y);
    g_eB[e] = make_float4(midx, midy, half, sq);
    g_eC[e] = make_float2(dda, __uint_as_float(packed));
    int p = atomicAdd(&g_bcnt[b], 1);
    g_blist[b * MAXE + p] = e;
}

// 3) Sparse compute over same-batch pairs only; scatter rare nonzeros.
__global__ void __launch_bounds__(BLK)
compute_kernel(float* __restrict__ out, int E, int writeBig) {
    const int i0 = blockIdx.x * TI;
    float* __restrict__ outM = out + 1;
    float* __restrict__ outS = out + 1 + (size_t)E * (size_t)E;

    unsigned long long accQ = 0ull;
    unsigned int       cnt  = 0u;

#pragma unroll 1
    for (int a = 0; a < TI; a++) {
        int i = i0 + a;
        if (i >= E) break;
        float4 iA = g_eA[i], iB = g_eB[i];
        float2 iC = g_eC[i];
        unsigned int pi = __float_as_uint(iC.y);
        int bi = (int)(pi >> 24);
        unsigned int si = (pi >> 12) & 0xFFFu, di = pi & 0xFFFu;
        int Lb = g_bcnt[bi];
        const int* lst = g_blist + bi * MAXE;
        for (int k = threadIdx.x; k < Lb; k += BLK) {
            int j = lst[k];
            if (j <= i) continue;
            float2 jC = g_eC[j];
            unsigned int pj = __float_as_uint(jC.y);
            unsigned int sj = (pj >> 12) & 0xFFFu, dj = pj & 0xFFFu;
            if ((si == sj) | (si == dj) | (di == sj) | (di == dj)) continue;
            float4 jB = g_eB[j];
            float dx = iB.x - jB.x;
            float dy = iB.y - jB.y;
            float reach = iB.z + jB.z + 0.15f;
            if (dx * dx + dy * dy >= reach * reach) continue;  // dist < reach
            cnt++;                                             // n_pairs
            float4 jA = g_eA[j];
            // Segment-segment min distance (reference order of clamps)
            float A  = iB.w;       // sq_i (clamped)
            float Ee = jB.w;       // sq_j (clamped)
            float b  = iA.z * jA.z + iA.w * jA.w;
            float c  = iC.x - (iA.z * jA.x + iA.w * jA.y);
            float f  = (iA.x * jA.z + iA.y * jA.w) - jC.x;
            float denom = fmaxf(A * Ee - b * b, 1e-12f);
            float s = __fdiv_rn(b * f - c * Ee, denom);
            s = fminf(fmaxf(s, 0.0f), 1.0f);
            float t = fminf(fmaxf(__fdiv_rn(b * s + f, Ee), 0.0f), 1.0f);
            s = fminf(fmaxf(__fdiv_rn(b * t - c, A), 0.0f), 1.0f);
            float cax = iA.x + s * iA.z;
            float cay = iA.y + s * iA.w;
            float cbx = jA.x + t * jA.z;
            float cby = jA.y + t * jA.w;
            float ddx = cax - cbx, ddy = cay - cby;
            float dmin = __fsqrt_rn(ddx * ddx + ddy * ddy);
            float pl = fmaxf(0.001f - dmin, 0.0f);
            if (pl > 0.0f) {
                accQ += (unsigned long long)
                    __double2ll_rn((double)pl * 1099511627776.0);
                if (writeBig) {
                    size_t off = (size_t)i * (size_t)E + (size_t)j;
                    outM[off] = 1.0f;   // mask & (pair_loss > 0)
                    outS[off] = pl;     // pair_loss
                }
            }
        }
    }

    // Block reduction -> one spread atomic per block
#pragma unroll
    for (int o = 16; o; o >>= 1) {
        accQ += __shfl_xor_sync(0xffffffffu, accQ, o);
        cnt  += __shfl_xor_sync(0xffffffffu, cnt,  o);
    }
    __shared__ unsigned long long sQ[BLK / 32];
    __shared__ unsigned int       sC[BLK / 32];
    int w = threadIdx.x >> 5;
    if ((threadIdx.x & 31) == 0) { sQ[w] = accQ; sC[w] = cnt; }
    __syncthreads();
    if (threadIdx.x == 0) {
        unsigned long long q = 0ull; unsigned int c = 0u;
#pragma unroll
        for (int k = 0; k < BLK / 32; k++) { q += sQ[k]; c += sC[k]; }
        if (q | (unsigned long long)c) {
            atomicAdd(&g_Acc[blockIdx.x], q);
            atomicAdd(&g_Cnt[blockIdx.x], (unsigned long long)c);
        }
    }
}

// 4) Final reduction -> out[0]
__global__ void finalize_kernel(float* __restrict__ out, int naccs) {
    __shared__ unsigned long long sQ[256];
    __shared__ unsigned long long sC[256];
    unsigned long long q = 0ull, c = 0ull;
    for (int k = threadIdx.x; k < naccs; k += 256) {
        q += g_Acc[k];
        c += g_Cnt[k];
    }
    sQ[threadIdx.x] = q; sC[threadIdx.x] = c;
    __syncthreads();
    for (int st = 128; st; st >>= 1) {
        if (threadIdx.x < st) {
            sQ[threadIdx.x] += sQ[threadIdx.x + st];
            sC[threadIdx.x] += sC[threadIdx.x + st];
        }
        __syncthreads();
    }
    if (threadIdx.x == 0) {
        double sum = (double)sQ[0] * (1.0 / 1099511627776.0);
        unsigned long long n = sC[0] ? sC[0] : 1ull;
        out[0] = (float)(sum / (double)n);
    }
}

extern "C" void kernel_launch(void* const* d_in, const int* in_sizes, int n_in,
                              void* d_out, int out_size) {
    const float* pos = (const float*)d_in[0];
    // d_in[1] = adjacency: unused by the reference computation
    const int*   ei  = (const int*)d_in[2];

    int E     = in_sizes[2] / 2;
    int nodes = in_sizes[0] / 2;
    int N     = in_sizes[1] / nodes;
    int nblocks = (E + TI - 1) / TI;

    long long need = 1ll + 2ll * (long long)E * (long long)E;
    int writeBig = ((long long)out_size >= need) ? 1 : 0;

    float* out = (float*)d_out;

    // 1) zero-fill planes [1, 1+2E^2) + bookkeeping
    long long start = 1, end = 1 + 2ll * (long long)E * (long long)E;
    if (!writeBig) end = start;   // still resets bookkeeping
    fill_kernel<<<1184, BLK>>>(out, start, 1 + 2ll * (long long)E * (long long)E,
                               writeBig);

    // 2) tables + batch lists
    prep_kernel<<<(E + 127) / 128, 128>>>(pos, ei, E, N, nodes);

    // 3) sparse same-batch compute + scatter
    compute_kernel<<<nblocks, BLK>>>(out, E, writeBig);

    // 4) loss
    finalize_kernel<<<1, 256>>>(out, min(nblocks, NACC));
}

// round 7
// speedup vs baseline: 1.4822x; 1.0140x over previous
#include <cuda_runtime.h>
#include <cuda_bf16.h>
#include <cstdint>

// ---------------------------------------------------------------------------
// SpatialNonIntersectionAxiom — sparse formulation, minimal graph.
// out[0]=loss, out[1..1+E^2)=violation_mask, out[1+E^2..1+2E^2)=scores (f32).
//
// Nodes: memset(bookkeeping) -> memset(planes) -> prep -> compute.
// compute does the final loss reduction via a last-block pattern (integer
// atomics only -> bit-deterministic across graph replays).
// ---------------------------------------------------------------------------

#define MAXE 8192
#define MAXB 64
#define BLK  256
#define TI   8

// Per-edge tables (__device__ globals: no allocs allowed)
__device__ float4 g_eA[MAXE];             // p_src.x, p_src.y, d1.x, d1.y
__device__ float4 g_eB[MAXE];             // mid.x, mid.y, half, sq(clamped)
__device__ float2 g_eC[MAXE];             // d1·p_src, packed(b<<24|src<<12|dst)
__device__ int    g_blist[MAXB * MAXE];   // per-batch edge lists

// Bookkeeping cleared by one small memset each call
struct Bookkeep {
    unsigned long long totQ;   // fixed-point 2^-40 loss sum
    unsigned long long totC;   // candidate count (n_pairs)
    unsigned int done;         // finished-block counter
    unsigned int pad;
    int bcnt[MAXB];            // per-batch list lengths
};
__device__ Bookkeep g_bk;

// Per-edge tables + per-batch lists (list order irrelevant downstream).
__global__ void prep_kernel(const float* __restrict__ pos,
                            const int* __restrict__ ei,
                            int E, int N, int nodes) {
    int e = blockIdx.x * blockDim.x + threadIdx.x;
    if (e >= E) return;
    int s = ei[e];
    int d = ei[E + e];
    s = min(max(s, 0), nodes - 1);
    d = min(max(d, 0), nodes - 1);
    float psx = pos[2 * s],  psy = pos[2 * s + 1];
    float pdx = pos[2 * d],  pdy = pos[2 * d + 1];
    float d1x = pdx - psx,   d1y = pdy - psy;
    float rawsq = d1x * d1x + d1y * d1y;
    float sq    = fmaxf(rawsq, 1e-12f);
    float half  = __fsqrt_rn(rawsq) * 0.5f;
    float midx  = (psx + pdx) * 0.5f;
    float midy  = (psy + pdy) * 0.5f;
    float dda   = d1x * psx + d1y * psy;
    int b = min(s / N, MAXB - 1);
    unsigned int packed = ((unsigned int)b << 24)
                        | (((unsigned int)s & 0xFFFu) << 12)
                        | ((unsigned int)d & 0xFFFu);
    g_eA[e] = make_float4(psx, psy, d1x, d1y);
    g_eB[e] = make_float4(midx, midy, half, sq);
    g_eC[e] = make_float2(dda, __uint_as_float(packed));
    int p = atomicAdd(&g_bk.bcnt[b], 1);
    g_blist[b * MAXE + p] = e;
}

// Sparse same-batch compute; scatter rare nonzeros; last block writes out[0].
__global__ void __launch_bounds__(BLK)
compute_kernel(float* __restrict__ out, int E, int writeBig) {
    const int i0 = blockIdx.x * TI;
    float* __restrict__ outM = out + 1;
    float* __restrict__ outS = out + 1 + (size_t)E * (size_t)E;

    unsigned long long accQ = 0ull;
    unsigned int       cnt  = 0u;

#pragma unroll 1
    for (int a = 0; a < TI; a++) {
        int i = i0 + a;
        if (i >= E) break;
        float4 iA = g_eA[i], iB = g_eB[i];
        float2 iC = g_eC[i];
        unsigned int pi = __float_as_uint(iC.y);
        int bi = (int)(pi >> 24);
        unsigned int si = (pi >> 12) & 0xFFFu, di = pi & 0xFFFu;
        int Lb = g_bk.bcnt[bi];
        const int* lst = g_blist + bi * MAXE;
        for (int k = threadIdx.x; k < Lb; k += BLK) {
            int j = lst[k];
            if (j <= i) continue;
            float2 jC = g_eC[j];
            unsigned int pj = __float_as_uint(jC.y);
            unsigned int sj = (pj >> 12) & 0xFFFu, dj = pj & 0xFFFu;
            if ((si == sj) | (si == dj) | (di == sj) | (di == dj)) continue;
            float4 jB = g_eB[j];
            float dx = iB.x - jB.x;
            float dy = iB.y - jB.y;
            float reach = iB.z + jB.z + 0.15f;
            if (dx * dx + dy * dy >= reach * reach) continue;  // dist < reach
            cnt++;                                             // n_pairs
            float4 jA = g_eA[j];
            // Segment-segment min distance (reference clamp order)
            float A  = iB.w;       // sq_i (clamped)
            float Ee = jB.w;       // sq_j (clamped)
            float b  = iA.z * jA.z + iA.w * jA.w;
            float c  = iC.x - (iA.z * jA.x + iA.w * jA.y);
            float f  = (iA.x * jA.z + iA.y * jA.w) - jC.x;
            float denom = fmaxf(A * Ee - b * b, 1e-12f);
            float s = __fdiv_rn(b * f - c * Ee, denom);
            s = fminf(fmaxf(s, 0.0f), 1.0f);
            float t = fminf(fmaxf(__fdiv_rn(b * s + f, Ee), 0.0f), 1.0f);
            s = fminf(fmaxf(__fdiv_rn(b * t - c, A), 0.0f), 1.0f);
            float cax = iA.x + s * iA.z;
            float cay = iA.y + s * iA.w;
            float cbx = jA.x + t * jA.z;
            float cby = jA.y + t * jA.w;
            float ddx = cax - cbx, ddy = cay - cby;
            float dmin = __fsqrt_rn(ddx * ddx + ddy * ddy);
            float pl = fmaxf(0.001f - dmin, 0.0f);
            if (pl > 0.0f) {
                accQ += (unsigned long long)
                    __double2ll_rn((double)pl * 1099511627776.0);
                if (writeBig) {
                    size_t off = (size_t)i * (size_t)E + (size_t)j;
                    outM[off] = 1.0f;   // mask & (pair_loss > 0)
                    outS[off] = pl;     // pair_loss
                }
            }
        }
    }

    // Block reduction
#pragma unroll
    for (int o = 16; o; o >>= 1) {
        accQ += __shfl_xor_sync(0xffffffffu, accQ, o);
        cnt  += __shfl_xor_sync(0xffffffffu, cnt,  o);
    }
    __shared__ unsigned long long sQ[BLK / 32];
    __shared__ unsigned int       sC[BLK / 32];
    int w = threadIdx.x >> 5;
    if ((threadIdx.x & 31) == 0) { sQ[w] = accQ; sC[w] = cnt; }
    __syncthreads();

    if (threadIdx.x == 0) {
        unsigned long long q = 0ull; unsigned int c = 0u;
#pragma unroll
        for (int k = 0; k < BLK / 32; k++) { q += sQ[k]; c += sC[k]; }
        if (q) atomicAdd(&g_bk.totQ, q);
        if (c) atomicAdd(&g_bk.totC, (unsigned long long)c);
        __threadfence();
        unsigned int old = atomicAdd(&g_bk.done, 1u);
        if (old == gridDim.x - 1) {
            // Last block: all partials visible (fence + atomic ordering)
            unsigned long long tq = atomicAdd(&g_bk.totQ, 0ull);
            unsigned long long tc = atomicAdd(&g_bk.totC, 0ull);
            double sum = (double)tq * (1.0 / 1099511627776.0);
            unsigned long long n = tc ? tc : 1ull;
            out[0] = (float)(sum / (double)n);
        }
    }
}

extern "C" void kernel_launch(void* const* d_in, const int* in_sizes, int n_in,
                              void* d_out, int out_size) {
    const float* pos = (const float*)d_in[0];
    // d_in[1] = adjacency: unused by the reference computation
    const int*   ei  = (const int*)d_in[2];

    int E     = in_sizes[2] / 2;
    int nodes = in_sizes[0] / 2;
    int N     = in_sizes[1] / nodes;
    int nblocks = (E + TI - 1) / TI;

    long long need = 1ll + 2ll * (long long)E * (long long)E;
    int writeBig = ((long long)out_size >= need) ? 1 : 0;

    float* out = (float*)d_out;

    // 1) Clear bookkeeping (tiny memset node; pure host symbol lookup first)
    void* bkPtr = nullptr;
    cudaGetSymbolAddress(&bkPtr, g_bk);
    cudaMemsetAsync(bkPtr, 0, sizeof(Bookkeep));

    // 2) Zero-fill both output planes (driver fill at DRAM write rate)
    if (writeBig) {
        cudaMemsetAsync(out + 1, 0,
                        2ull * (size_t)E * (size_t)E * sizeof(float));
    } else if (out_size > 1) {
        cudaMemsetAsync(out + 1, 0, ((size_t)out_size - 1) * sizeof(float));
    }

    // 3) tables + batch lists
    prep_kernel<<<(E + 127) / 128, 128>>>(pos, ei, E, N, nodes);

    // 4) sparse same-batch compute + scatter + inline final reduction
    compute_kernel<<<nblocks, BLK>>>(out, E, writeBig);
}

// round 8
// speedup vs baseline: 1.7906x; 1.2081x over previous
#include <cuda_runtime.h>
#include <cuda_bf16.h>
#include <cstdint>

// ---------------------------------------------------------------------------
// SpatialNonIntersectionAxiom — sparse, SMEM-staged batch pair enumeration.
// out[0]=loss, out[1..1+E^2)=violation_mask, out[1+E^2..1+2E^2)=scores (f32).
//
// Graph: memset(bookkeeping) -> memset(planes) -> prep -> compute.
// compute enumerates unordered same-batch pairs from SMEM-staged tables and
// finishes the loss reduction with a last-block pattern (integer atomics ->
// bit-deterministic across replays).
// ---------------------------------------------------------------------------

#define MAXE  8192
#define MAXB  64
#define BLK   256
#define CHNK  96      // chunks per batch (grid.x)
#define SMAXL 1024    // max staged batch size

// Per-edge tables (__device__ globals: no allocs allowed)
__device__ float4 g_eA[MAXE];             // p_src.x, p_src.y, d1.x, d1.y
__device__ float4 g_eB[MAXE];             // mid.x, mid.y, half, sq(clamped)
__device__ float2 g_eC[MAXE];             // d1·p_src, packed(b<<24|s<<12|d)
__device__ int    g_blist[MAXB * MAXE];   // per-batch edge lists

struct Bookkeep {
    unsigned long long totQ;   // fixed-point 2^-40 loss sum
    unsigned long long totC;   // candidate count (n_pairs)
    unsigned int done;         // finished-block counter
    unsigned int pad;
    int bcnt[MAXB];            // per-batch list lengths
};
__device__ Bookkeep g_bk;

__global__ void prep_kernel(const float* __restrict__ pos,
                            const int* __restrict__ ei,
                            int E, int N, int nodes) {
    int e = blockIdx.x * blockDim.x + threadIdx.x;
    if (e >= E) return;
    int s = ei[e];
    int d = ei[E + e];
    s = min(max(s, 0), nodes - 1);
    d = min(max(d, 0), nodes - 1);
    float psx = pos[2 * s],  psy = pos[2 * s + 1];
    float pdx = pos[2 * d],  pdy = pos[2 * d + 1];
    float d1x = pdx - psx,   d1y = pdy - psy;
    float rawsq = d1x * d1x + d1y * d1y;
    float sq    = fmaxf(rawsq, 1e-12f);
    float half  = __fsqrt_rn(rawsq) * 0.5f;
    float midx  = (psx + pdx) * 0.5f;
    float midy  = (psy + pdy) * 0.5f;
    float dda   = d1x * psx + d1y * psy;
    int b = min(s / N, MAXB - 1);
    unsigned int packed = ((unsigned int)b << 24)
                        | (((unsigned int)s & 0xFFFu) << 12)
                        | ((unsigned int)d & 0xFFFu);
    g_eA[e] = make_float4(psx, psy, d1x, d1y);
    g_eB[e] = make_float4(midx, midy, half, sq);
    g_eC[e] = make_float2(dda, __uint_as_float(packed));
    int p = atomicAdd(&g_bk.bcnt[b], 1);
    g_blist[b * MAXE + p] = e;
}

// dmin/pair-loss for ordered (i<j) pair given register tuples.
__device__ __forceinline__ float seg_loss(
    const float4& iA, const float4& iB, const float2& iC,
    const float4& jA, const float4& jB, const float2& jC)
{
    float A  = iB.w;       // sq_i (clamped)
    float Ee = jB.w;       // sq_j (clamped)
    float b  = iA.z * jA.z + iA.w * jA.w;
    float c  = iC.x - (iA.z * jA.x + iA.w * jA.y);
    float f  = (iA.x * jA.z + iA.y * jA.w) - jC.x;
    float denom = fmaxf(A * Ee - b * b, 1e-12f);
    float s = __fdiv_rn(b * f - c * Ee, denom);
    s = fminf(fmaxf(s, 0.0f), 1.0f);
    float t = fminf(fmaxf(__fdiv_rn(b * s + f, Ee), 0.0f), 1.0f);
    s = fminf(fmaxf(__fdiv_rn(b * t - c, A), 0.0f), 1.0f);
    float cax = iA.x + s * iA.z;
    float cay = iA.y + s * iA.w;
    float cbx = jA.x + t * jA.z;
    float cby = jA.y + t * jA.w;
    float ddx = cax - cbx, ddy = cay - cby;
    float dmin = __fsqrt_rn(ddx * ddx + ddy * ddy);
    return fmaxf(0.001f - dmin, 0.0f);
}

// grid = (CHNK, B). Block stages batch tables in SMEM, enumerates unordered
// pairs (ki < kj) with balanced strided row assignment.
__global__ void __launch_bounds__(BLK)
compute_kernel(float* __restrict__ out, int E, int writeBig, int totBlocks) {
    __shared__ float4 sA[SMAXL];
    __shared__ float4 sB[SMAXL];
    __shared__ float2 sC[SMAXL];
    __shared__ int    sIdx[SMAXL];

    const int b = blockIdx.y;
    const int c = blockIdx.x;
    const int L = g_bk.bcnt[b];
    const int* lst = g_blist + b * MAXE;

    float* __restrict__ outM = out + 1;
    float* __restrict__ outS = out + 1 + (size_t)E * (size_t)E;

    unsigned long long accQ = 0ull;
    unsigned int       cnt  = 0u;

    if (L <= SMAXL) {
        // Stage the whole batch into SMEM
        for (int k = threadIdx.x; k < L; k += BLK) {
            int e = lst[k];
            sA[k] = g_eA[e]; sB[k] = g_eB[e]; sC[k] = g_eC[e]; sIdx[k] = e;
        }
        __syncthreads();

        for (int ki = c; ki < L; ki += CHNK) {
            float4 rA = sA[ki], rB = sB[ki];
            float2 rC = sC[ki];
            int    re = sIdx[ki];
            unsigned int pr = __float_as_uint(rC.y);
            unsigned int rs = (pr >> 12) & 0xFFFu, rd = pr & 0xFFFu;
            for (int kj = ki + 1 + threadIdx.x; kj < L; kj += BLK) {
                float2 qC = sC[kj];
                unsigned int pq = __float_as_uint(qC.y);
                unsigned int qs = (pq >> 12) & 0xFFFu, qd = pq & 0xFFFu;
                if ((rs == qs) | (rs == qd) | (rd == qs) | (rd == qd)) continue;
                float4 qB = sB[kj];
                float dx = rB.x - qB.x;
                float dy = rB.y - qB.y;
                float reach = rB.z + qB.z + 0.15f;
                if (dx * dx + dy * dy >= reach * reach) continue;
                cnt++;                                  // candidate (n_pairs)
                float4 qA = sA[kj];
                int    qe = sIdx[kj];
                // Orient: i = min(edge idx), j = max (reference upper-tri)
                bool sw = re > qe;
                float4 iA = sw ? qA : rA, jA = sw ? rA : qA;
                float4 iB = sw ? qB : rB, jB = sw ? rB : qB;
                float2 iC = sw ? qC : rC, jC = sw ? rC : qC;
                float pl = seg_loss(iA, iB, iC, jA, jB, jC);
                if (pl > 0.0f) {
                    accQ += (unsigned long long)
                        __double2ll_rn((double)pl * 1099511627776.0);
                    if (writeBig) {
                        int i = sw ? qe : re, j = sw ? re : qe;
                        size_t off = (size_t)i * (size_t)E + (size_t)j;
                        outM[off] = 1.0f;
                        outS[off] = pl;
                    }
                }
            }
        }
    } else {
        // Fallback: same enumeration from global tables (oversized batch)
        for (int ki = c; ki < L; ki += CHNK) {
            int re = lst[ki];
            float4 rA = g_eA[re], rB = g_eB[re];
            float2 rC = g_eC[re];
            unsigned int pr = __float_as_uint(rC.y);
            unsigned int rs = (pr >> 12) & 0xFFFu, rd = pr & 0xFFFu;
            for (int kj = ki + 1 + threadIdx.x; kj < L; kj += BLK) {
                int qe = lst[kj];
                float2 qC = g_eC[qe];
                unsigned int pq = __float_as_uint(qC.y);
                unsigned int qs = (pq >> 12) & 0xFFFu, qd = pq & 0xFFFu;
                if ((rs == qs) | (rs == qd) | (rd == qs) | (rd == qd)) continue;
                float4 qB = g_eB[qe];
                float dx = rB.x - qB.x;
                float dy = rB.y - qB.y;
                float reach = rB.z + qB.z + 0.15f;
                if (dx * dx + dy * dy >= reach * reach) continue;
                cnt++;
                float4 qA = g_eA[qe];
                bool sw = re > qe;
                float4 iA = sw ? qA : rA, jA = sw ? rA : qA;
                float4 iB = sw ? qB : rB, jB = sw ? rB : qB;
                float2 iC = sw ? qC : rC, jC = sw ? rC : qC;
                float pl = seg_loss(iA, iB, iC, jA, jB, jC);
                if (pl > 0.0f) {
                    accQ += (unsigned long long)
                        __double2ll_rn((double)pl * 1099511627776.0);
                    if (writeBig) {
                        int i = sw ? qe : re, j = sw ? re : qe;
                        size_t off = (size_t)i * (size_t)E + (size_t)j;
                        outM[off] = 1.0f;
                        outS[off] = pl;
                    }
                }
            }
        }
    }

    // Block reduction -> global totals; last block writes out[0]
#pragma unroll
    for (int o = 16; o; o >>= 1) {
        accQ += __shfl_xor_sync(0xffffffffu, accQ, o);
        cnt  += __shfl_xor_sync(0xffffffffu, cnt,  o);
    }
    __shared__ unsigned long long rQ[BLK / 32];
    __shared__ unsigned int       rC2[BLK / 32];
    int w = threadIdx.x >> 5;
    if ((threadIdx.x & 31) == 0) { rQ[w] = accQ; rC2[w] = cnt; }
    __syncthreads();
    if (threadIdx.x == 0) {
        unsigned long long q = 0ull; unsigned int cc = 0u;
#pragma unroll
        for (int k = 0; k < BLK / 32; k++) { q += rQ[k]; cc += rC2[k]; }
        if (q) atomicAdd(&g_bk.totQ, q);
        if (cc) atomicAdd(&g_bk.totC, (unsigned long long)cc);
        __threadfence();
        unsigned int old = atomicAdd(&g_bk.done, 1u);
        if (old == (unsigned int)totBlocks - 1u) {
            unsigned long long tq = atomicAdd(&g_bk.totQ, 0ull);
            unsigned long long tc = atomicAdd(&g_bk.totC, 0ull);
            double sum = (double)tq * (1.0 / 1099511627776.0);
            unsigned long long n = tc ? tc : 1ull;
            out[0] = (float)(sum / (double)n);
        }
    }
}

extern "C" void kernel_launch(void* const* d_in, const int* in_sizes, int n_in,
                              void* d_out, int out_size) {
    const float* pos = (const float*)d_in[0];
    // d_in[1] = adjacency: unused by the reference computation
    const int*   ei  = (const int*)d_in[2];

    int E     = in_sizes[2] / 2;
    int nodes = in_sizes[0] / 2;
    int N     = in_sizes[1] / nodes;
    int B     = min((nodes + N - 1) / N, MAXB);

    long long need = 1ll + 2ll * (long long)E * (long long)E;
    int writeBig = ((long long)out_size >= need) ? 1 : 0;

    float* out = (float*)d_out;

    // 1) Clear bookkeeping
    void* bkPtr = nullptr;
    cudaGetSymbolAddress(&bkPtr, g_bk);
    cudaMemsetAsync(bkPtr, 0, sizeof(Bookkeep));

    // 2) Zero-fill output planes (DRAM-write-rate driver fill)
    if (writeBig) {
        cudaMemsetAsync(out + 1, 0,
                        2ull * (size_t)E * (size_t)E * sizeof(float));
    } else if (out_size > 1) {
        cudaMemsetAsync(out + 1, 0, ((size_t)out_size - 1) * sizeof(float));
    }

    // 3) tables + batch lists
    prep_kernel<<<(E + 127) / 128, 128>>>(pos, ei, E, N, nodes);

    // 4) SMEM-staged unordered-pair compute + scatter + final reduction
    dim3 grid(CHNK, B);
    int totBlocks = CHNK * B;
    compute_kernel<<<grid, BLK>>>(out, E, writeBig, totBlocks);
}